// round 3
// baseline (speedup 1.0000x reference)
#include <cuda_runtime.h>
#include <cstdint>

// SigmoidFlow: B=2048, D=512, NDIM=16
// out[0..B*D) = xnew ; out[B*D..B*D+B) = logdet
//
// HBM-bound -> cp.async.bulk (UBLKCP) + mbarrier ring pipeline into SMEM.
// Math identities (same as R2):
//  lse_k(log_softmax(wl)+logsig(pre)+logsig(-pre)+log a) = log(sum ew*a*t*g^2) - log(W)
//  g_k via single-rcp cofactor trick; xnew/logdet from 3 logs total.

#define TPB 256
#define CHUNK 64                 // elements per stage
#define DEPTH 3                  // ring depth

__device__ __forceinline__ float fast_rcp(float v) {
    float r; asm("rcp.approx.f32 %0, %1;" : "=f"(r) : "f"(v)); return r;
}
__device__ __forceinline__ uint32_t smem_u32(const void* p) {
    uint32_t a;
    asm("{ .reg .u64 t; cvta.to.shared.u64 t, %1; cvt.u32.u64 %0, t; }" : "=r"(a) : "l"(p));
    return a;
}
__device__ __forceinline__ void mbar_init(uint32_t mbar, uint32_t cnt) {
    asm volatile("mbarrier.init.shared.b64 [%0], %1;" :: "r"(mbar), "r"(cnt) : "memory");
}
__device__ __forceinline__ void mbar_expect_tx(uint32_t mbar, uint32_t bytes) {
    asm volatile("mbarrier.arrive.expect_tx.shared.b64 _, [%0], %1;" :: "r"(mbar), "r"(bytes) : "memory");
}
__device__ __forceinline__ void bulk_g2s(uint32_t dst, const void* src, uint32_t bytes, uint32_t mbar) {
    asm volatile("cp.async.bulk.shared::cta.global.mbarrier::complete_tx::bytes [%0], [%1], %2, [%3];"
                 :: "r"(dst), "l"(src), "r"(bytes), "r"(mbar) : "memory");
}
__device__ __forceinline__ void mbar_wait(uint32_t mbar, uint32_t parity) {
    uint32_t done;
    asm volatile("{\n\t.reg .pred p;\n\t"
                 "mbarrier.try_wait.parity.acquire.cta.shared::cta.b64 p, [%1], %2;\n\t"
                 "selp.b32 %0, 1, 0, p;\n\t}"
                 : "=r"(done) : "r"(mbar), "r"(parity) : "memory");
    if (!done) {
        asm volatile("{\n\t.reg .pred P1;\n\t"
                     "WL_%=:\n\t"
                     "mbarrier.try_wait.parity.acquire.cta.shared::cta.b64 P1, [%0], %1, 0x989680;\n\t"
                     "@P1 bra.uni WD_%=;\n\t"
                     "bra.uni WL_%=;\n\t"
                     "WD_%=:\n\t}"
                     :: "r"(mbar), "r"(parity) : "memory");
    }
}

__device__ __forceinline__ void sf_compute(float4 av, float4 bv, float4 wv, float xv,
                                           float& Wl, float& Sl, float& Dl)
{
    float a_[4] = {av.x, av.y, av.z, av.w};
    float b_[4] = {bv.x, bv.y, bv.z, bv.w};
    float wl[4] = {wv.x, wv.y, wv.z, wv.w};

    float asp[4], t[4], onet[4], ew[4];
    #pragma unroll
    for (int j = 0; j < 4; ++j) {
        float ea  = __expf(a_[j]);
        asp[j]    = __logf(1.0f + ea);            // softplus
        float pre = fmaf(asp[j], xv, b_[j]);
        t[j]      = __expf(-pre);
        onet[j]   = 1.0f + t[j];
        ew[j]     = __expf(wl[j]);
    }
    float p01 = onet[0] * onet[1];
    float p23 = onet[2] * onet[3];
    float iP  = fast_rcp(p01 * p23);
    float h0  = (onet[1] * p23) * iP;
    float h1  = (onet[0] * p23) * iP;
    float h2  = (p01 * onet[3]) * iP;
    float h3  = (p01 * onet[2]) * iP;

    Wl = (ew[0] + ew[1]) + (ew[2] + ew[3]);
    Sl = fmaf(ew[3], h3, fmaf(ew[2], h2, fmaf(ew[1], h1, ew[0] * h0)));
    float d0 = (ew[0] * asp[0]) * (t[0] * h0 * h0);
    float d1 = (ew[1] * asp[1]) * (t[1] * h1 * h1);
    float d2 = (ew[2] * asp[2]) * (t[2] * h2 * h2);
    float d3 = (ew[3] * asp[3]) * (t[3] * h3 * h3);
    Dl = (d0 + d1) + (d2 + d3);
}

struct Stage {
    float dsp[CHUNK * 48];   // 12288 B
    float x[CHUNK];          // 256 B
};
#define STAGE_BYTES (CHUNK * 48 * 4 + CHUNK * 4)   // 12544

// D must be a multiple of CHUNK for this kernel (D=512 -> 8 stages).
__global__ __launch_bounds__(TPB, 4)
void sf_bulk_kernel(const float* __restrict__ x,
                    const float* __restrict__ logdet_in,
                    const float* __restrict__ dsp,
                    float* __restrict__ out,
                    int B, int D)
{
    __shared__ Stage stg[DEPTH];
    __shared__ unsigned long long mbar[DEPTH];
    __shared__ float s_part[TPB / 32];

    const int b    = blockIdx.x;
    const int tid  = threadIdx.x;
    const int lane = tid & 31;
    const int wid  = tid >> 5;
    const int q    = lane & 3;
    const int e    = wid * 8 + (lane >> 2);   // 0..63 element within chunk

    const float ONE_MD = 1.0f - 1e-6f;
    const float HALF_D = 0.5e-6f;
    const float LOG1MD = -1.0000005e-6f;

    const int NST = D / CHUNK;

    uint32_t mb[DEPTH];
    #pragma unroll
    for (int s = 0; s < DEPTH; ++s) mb[s] = smem_u32(&mbar[s]);

    const float* dsp_row = dsp + (long long)b * D * 48;
    const float* x_row   = x + (long long)b * D;

    if (tid == 0) {
        #pragma unroll
        for (int s = 0; s < DEPTH; ++s) mbar_init(mb[s], 1);
    }
    __syncthreads();

    // Prologue: fill slots 0..DEPTH-1
    if (tid == 0) {
        #pragma unroll
        for (int s = 0; s < DEPTH; ++s) {
            if (s < NST) {
                mbar_expect_tx(mb[s], STAGE_BYTES);
                bulk_g2s(smem_u32(stg[s].dsp), dsp_row + (long long)s * CHUNK * 48,
                         CHUNK * 48 * 4, mb[s]);
                bulk_g2s(smem_u32(stg[s].x), x_row + s * CHUNK, CHUNK * 4, mb[s]);
            }
        }
    }

    float acc = 0.0f;

    for (int st = 0; st < NST; ++st) {
        const int slot = st % DEPTH;
        const uint32_t parity = (uint32_t)((st / DEPTH) & 1);

        mbar_wait(mb[slot], parity);

        const float4* p = (const float4*)(stg[slot].dsp + e * 48);
        const float4 av = p[q];
        const float4 bv = p[4 + q];
        const float4 wv = p[8 + q];
        const float  xv = stg[slot].x[e];

        float Wl, Sl, Dl;
        sf_compute(av, bv, wv, xv, Wl, Sl, Dl);

        // reduce across the 4-lane group
        Wl += __shfl_xor_sync(0xffffffffu, Wl, 1);
        Sl += __shfl_xor_sync(0xffffffffu, Sl, 1);
        Dl += __shfl_xor_sync(0xffffffffu, Dl, 1);
        Wl += __shfl_xor_sync(0xffffffffu, Wl, 2);
        Sl += __shfl_xor_sync(0xffffffffu, Sl, 2);
        Dl += __shfl_xor_sync(0xffffffffu, Dl, 2);

        const float hw = HALF_D * Wl;
        const float N1 = fmaf(ONE_MD, Sl, hw);
        const float N2 = fmaf(ONE_MD, Wl - Sl, hw);
        const float l1 = __logf(N1);
        const float l2 = __logf(N2);
        const float l3 = __logf(Dl * Wl);

        const long long idx = (long long)b * D + st * CHUNK + e;
        if (q == 0) __stcs(out + idx, l1 - l2);    // xnew
        acc += l3 - l1 - l2 + LOG1MD;              // replicated x4

        __syncthreads();   // all threads done reading this slot

        if (tid == 0 && st + DEPTH < NST) {
            const int ns = st + DEPTH;
            mbar_expect_tx(mb[slot], STAGE_BYTES);
            bulk_g2s(smem_u32(stg[slot].dsp), dsp_row + (long long)ns * CHUNK * 48,
                     CHUNK * 48 * 4, mb[slot]);
            bulk_g2s(smem_u32(stg[slot].x), x_row + ns * CHUNK, CHUNK * 4, mb[slot]);
        }
    }

    // block logdet reduction (each element counted 4x -> scale 0.25)
    #pragma unroll
    for (int m = 16; m >= 1; m >>= 1)
        acc += __shfl_xor_sync(0xffffffffu, acc, m);
    if (lane == 0) s_part[wid] = acc;
    __syncthreads();

    if (wid == 0) {
        float v = (lane < (TPB / 32)) ? s_part[lane] : 0.0f;
        #pragma unroll
        for (int m = 4; m >= 1; m >>= 1)
            v += __shfl_xor_sync(0xffffffffu, v, m);
        if (lane == 0)
            out[(long long)B * D + b] = 0.25f * v + __ldg(logdet_in + b);
    }
}

// Generic fallback (any D), LDG-based — same math.
__global__ __launch_bounds__(512)
void sf_kernel_gen(const float* __restrict__ x,
                   const float* __restrict__ logdet_in,
                   const float* __restrict__ dsp,
                   float* __restrict__ out,
                   int B, int D)
{
    const int b    = blockIdx.x;
    const int tid  = threadIdx.x;
    const int lane = tid & 31;
    const int wid  = tid >> 5;
    const int q    = lane & 3;
    const int e_in_block = wid * 8 + (lane >> 2);

    const float ONE_MD = 1.0f - 1e-6f;
    const float HALF_D = 0.5e-6f;
    const float LOG1MD = -1.0000005e-6f;

    __shared__ float s_part[16];
    float acc = 0.0f;

    const int niter = (D + 127) / 128;
    for (int it = 0; it < niter; ++it) {
        const int d = it * 128 + e_in_block;
        if (d < D) {
            const long long idx = (long long)b * D + d;
            const float4* p = (const float4*)(dsp + idx * 48);
            const float4 av = __ldcs(p + q);
            const float4 bv = __ldcs(p + 4 + q);
            const float4 wv = __ldcs(p + 8 + q);
            const float  xv = __ldcs(x + idx);

            float Wl, Sl, Dl;
            sf_compute(av, bv, wv, xv, Wl, Sl, Dl);

            Wl += __shfl_xor_sync(0xffffffffu, Wl, 1);
            Sl += __shfl_xor_sync(0xffffffffu, Sl, 1);
            Dl += __shfl_xor_sync(0xffffffffu, Dl, 1);
            Wl += __shfl_xor_sync(0xffffffffu, Wl, 2);
            Sl += __shfl_xor_sync(0xffffffffu, Sl, 2);
            Dl += __shfl_xor_sync(0xffffffffu, Dl, 2);

            const float hw = HALF_D * Wl;
            const float N1 = fmaf(ONE_MD, Sl, hw);
            const float N2 = fmaf(ONE_MD, Wl - Sl, hw);
            const float l1 = __logf(N1);
            const float l2 = __logf(N2);
            const float l3 = __logf(Dl * Wl);

            if (q == 0) __stcs(out + idx, l1 - l2);
            acc += l3 - l1 - l2 + LOG1MD;
        }
    }

    #pragma unroll
    for (int m = 16; m >= 1; m >>= 1)
        acc += __shfl_xor_sync(0xffffffffu, acc, m);
    if (lane == 0) s_part[wid] = acc;
    __syncthreads();

    if (wid == 0) {
        float v = (lane < 16) ? s_part[lane] : 0.0f;
        #pragma unroll
        for (int m = 8; m >= 1; m >>= 1)
            v += __shfl_xor_sync(0xffffffffu, v, m);
        if (lane == 0)
            out[(long long)B * D + b] = 0.25f * v + __ldg(logdet_in + b);
    }
}

extern "C" void kernel_launch(void* const* d_in, const int* in_sizes, int n_in,
                              void* d_out, int out_size)
{
    const float* x   = (const float*)d_in[0];
    const float* ld  = (const float*)d_in[1];
    const float* dsp = (const float*)d_in[2];
    float* out = (float*)d_out;

    const int B = in_sizes[1];
    const int D = in_sizes[0] / B;

    if ((D % CHUNK) == 0)
        sf_bulk_kernel<<<B, TPB>>>(x, ld, dsp, out, B, D);
    else
        sf_kernel_gen<<<B, 512>>>(x, ld, dsp, out, B, D);
}

// round 4
// speedup vs baseline: 1.1105x; 1.1105x over previous
#include <cuda_runtime.h>

// SigmoidFlow: B=2048, D=512, NDIM=16
// out[0..B*D) = xnew ; out[B*D..B*D+B) = logdet
//
// R4: single-wave launch shape. TPB=128 -> all 2048 row-blocks resident at
// once (148 SMs x up-to-16 CTAs), removing the 3.46-wave tail that capped
// DRAM at ~71% in R1-R3. Math identical to R2 (single-rcp cofactor trick,
// 3 logs per element epilogue).

#define TPB 128

__device__ __forceinline__ float fast_rcp(float v) {
    float r; asm("rcp.approx.f32 %0, %1;" : "=f"(r) : "f"(v)); return r;
}

__device__ __forceinline__ void sf_compute(float4 av, float4 bv, float4 wv, float xv,
                                           float& Wl, float& Sl, float& Dl)
{
    float a_[4] = {av.x, av.y, av.z, av.w};
    float b_[4] = {bv.x, bv.y, bv.z, bv.w};
    float wl[4] = {wv.x, wv.y, wv.z, wv.w};

    float asp[4], t[4], onet[4], ew[4];
    #pragma unroll
    for (int j = 0; j < 4; ++j) {
        float ea  = __expf(a_[j]);
        asp[j]    = __logf(1.0f + ea);            // softplus
        float pre = fmaf(asp[j], xv, b_[j]);
        t[j]      = __expf(-pre);
        onet[j]   = 1.0f + t[j];
        ew[j]     = __expf(wl[j]);
    }
    float p01 = onet[0] * onet[1];
    float p23 = onet[2] * onet[3];
    float iP  = fast_rcp(p01 * p23);
    float h0  = (onet[1] * p23) * iP;             // = sigm_0
    float h1  = (onet[0] * p23) * iP;
    float h2  = (p01 * onet[3]) * iP;
    float h3  = (p01 * onet[2]) * iP;

    Wl = (ew[0] + ew[1]) + (ew[2] + ew[3]);
    Sl = fmaf(ew[3], h3, fmaf(ew[2], h2, fmaf(ew[1], h1, ew[0] * h0)));
    float d0 = (ew[0] * asp[0]) * (t[0] * h0 * h0);
    float d1 = (ew[1] * asp[1]) * (t[1] * h1 * h1);
    float d2 = (ew[2] * asp[2]) * (t[2] * h2 * h2);
    float d3 = (ew[3] * asp[3]) * (t[3] * h3 * h3);
    Dl = (d0 + d1) + (d2 + d3);
}

__global__ __launch_bounds__(TPB, 16)
void sf_kernel(const float* __restrict__ x,
               const float* __restrict__ logdet_in,
               const float* __restrict__ dsp,
               float* __restrict__ out,
               int B, int D)
{
    const int b    = blockIdx.x;
    const int tid  = threadIdx.x;
    const int lane = tid & 31;
    const int wid  = tid >> 5;                 // 0..3
    const int q    = lane & 3;                 // component-group
    const int e_in_block = wid * 8 + (lane >> 2);   // 0..31 element per iter

    const float ONE_MD = 1.0f - 1e-6f;
    const float HALF_D = 0.5e-6f;
    const float LOG1MD = -1.0000005e-6f;

    __shared__ float s_part[TPB / 32];

    float acc = 0.0f;

    const int niter = (D + 31) / 32;
    for (int it = 0; it < niter; ++it) {
        const int d = it * 32 + e_in_block;
        if (d < D) {
            const long long idx = (long long)b * D + d;
            const float4* p = (const float4*)(dsp + idx * 48);
            const float4 av = __ldcs(p + q);
            const float4 bv = __ldcs(p + 4 + q);
            const float4 wv = __ldcs(p + 8 + q);
            const float  xv = __ldcs(x + idx);

            float Wl, Sl, Dl;
            sf_compute(av, bv, wv, xv, Wl, Sl, Dl);

            // reduce (W,S,D) across the 4-lane group
            Wl += __shfl_xor_sync(0xffffffffu, Wl, 1);
            Sl += __shfl_xor_sync(0xffffffffu, Sl, 1);
            Dl += __shfl_xor_sync(0xffffffffu, Dl, 1);
            Wl += __shfl_xor_sync(0xffffffffu, Wl, 2);
            Sl += __shfl_xor_sync(0xffffffffu, Sl, 2);
            Dl += __shfl_xor_sync(0xffffffffu, Dl, 2);

            const float hw = HALF_D * Wl;
            const float N1 = fmaf(ONE_MD, Sl, hw);
            const float N2 = fmaf(ONE_MD, Wl - Sl, hw);
            const float l1 = __logf(N1);
            const float l2 = __logf(N2);
            const float l3 = __logf(Dl * Wl);

            if (q == 0) __stcs(out + idx, l1 - l2);   // xnew
            acc += l3 - l1 - l2 + LOG1MD;             // replicated x4
        }
    }

    // warp + block reduction (each element counted 4x -> scale 0.25)
    #pragma unroll
    for (int m = 16; m >= 1; m >>= 1)
        acc += __shfl_xor_sync(0xffffffffu, acc, m);
    if (lane == 0) s_part[wid] = acc;
    __syncthreads();

    if (wid == 0) {
        float v = (lane < (TPB / 32)) ? s_part[lane] : 0.0f;
        v += __shfl_xor_sync(0xffffffffu, v, 2);
        v += __shfl_xor_sync(0xffffffffu, v, 1);
        if (lane == 0)
            out[(long long)B * D + b] = 0.25f * v + __ldg(logdet_in + b);
    }
}

extern "C" void kernel_launch(void* const* d_in, const int* in_sizes, int n_in,
                              void* d_out, int out_size)
{
    const float* x   = (const float*)d_in[0];   // (B, D)
    const float* ld  = (const float*)d_in[1];   // (B,)
    const float* dsp = (const float*)d_in[2];   // (B, D, 48)
    float* out = (float*)d_out;

    const int B = in_sizes[1];
    const int D = in_sizes[0] / B;

    sf_kernel<<<B, TPB>>>(x, ld, dsp, out, B, D);
}